// round 5
// baseline (speedup 1.0000x reference)
#include <cuda_runtime.h>
#include <cstdint>

#define NF        40960
#define MDIM      256
#define NB        2048
#define ROWS      (2*NB)              // 4096 feature rows (white then black)
#define ROW_BYTES (NF*4)              // 163840
#define TILE_BYTES 16384
#define TILE_FLOATS 4096
#define NTILES    (ROW_BYTES/TILE_BYTES)  // 10
#define NBUF      2
#define NSEG      8                   // per-row list segments (= warps)
#define SEG_CAP   32

// Transposed feature-transformer weights: ft_wT[f][m], 40960 x 256 fp32 = 41.9 MB
__device__ float g_ftwT[NF * MDIM];
// Compact nonzero index lists + counts: per (row, warp-segment)
__device__ int g_list[ROWS * NSEG * SEG_CAP];
__device__ int g_cnt[ROWS * NSEG];

// ---------------------------------------------------------------------------
// PTX helpers
// ---------------------------------------------------------------------------
__device__ __forceinline__ uint32_t smem_u32(const void* p) {
    uint32_t a;
    asm("{ .reg .u64 t; cvta.to.shared.u64 t, %1; cvt.u32.u64 %0, t; }"
        : "=r"(a) : "l"(p));
    return a;
}
__device__ __forceinline__ void mbar_init(uint32_t a, uint32_t cnt) {
    asm volatile("mbarrier.init.shared.b64 [%0], %1;" :: "r"(a), "r"(cnt) : "memory");
}
__device__ __forceinline__ void mbar_expect_tx(uint32_t a, uint32_t bytes) {
    asm volatile("mbarrier.arrive.expect_tx.shared.b64 _, [%0], %1;"
                 :: "r"(a), "r"(bytes) : "memory");
}
__device__ __forceinline__ void mbar_arrive(uint32_t a) {
    asm volatile("mbarrier.arrive.shared.b64 _, [%0];" :: "r"(a) : "memory");
}
__device__ __forceinline__ void mbar_wait(uint32_t a, uint32_t parity) {
    asm volatile(
        "{\n\t"
        ".reg .pred P;\n\t"
        "WL_%=:\n\t"
        "mbarrier.try_wait.parity.acquire.cta.shared::cta.b64 P, [%0], %1, 0x989680;\n\t"
        "@P bra WD_%=;\n\t"
        "bra WL_%=;\n\t"
        "WD_%=:\n\t"
        "}" :: "r"(a), "r"(parity) : "memory");
}
__device__ __forceinline__ void bulk_g2s(uint32_t dst, const void* src, uint32_t bytes,
                                         uint32_t mbar) {
    asm volatile(
        "cp.async.bulk.shared::cluster.global.mbarrier::complete_tx::bytes [%0], [%1], %2, [%3];"
        :: "r"(dst), "l"(src), "r"(bytes), "r"(mbar) : "memory");
}
__device__ __forceinline__ uint4 lds128(uint32_t a) {
    uint4 v;
    asm volatile("ld.shared.v4.u32 {%0,%1,%2,%3}, [%4];"
                 : "=r"(v.x), "=r"(v.y), "=r"(v.z), "=r"(v.w) : "r"(a));
    return v;
}

// ---------------------------------------------------------------------------
// Kernel 1: tiled transpose ft_w [256, 40960] -> g_ftwT [40960, 256]
// ---------------------------------------------------------------------------
__global__ __launch_bounds__(256) void transpose_ftw_kernel(const float* __restrict__ ft_w) {
    __shared__ float tile[32][33];
    const int f0 = blockIdx.x * 32;
    const int m0 = blockIdx.y * 32;
    const int t  = threadIdx.x;
    {
        const int m = t >> 3;
        const int q = t & 7;
        const float4 v = *reinterpret_cast<const float4*>(
            ft_w + (size_t)(m0 + m) * NF + f0 + q * 4);
        tile[m][q * 4 + 0] = v.x;
        tile[m][q * 4 + 1] = v.y;
        tile[m][q * 4 + 2] = v.z;
        tile[m][q * 4 + 3] = v.w;
    }
    __syncthreads();
    {
        const int f  = t >> 3;
        const int m4 = t & 7;
        float4 v;
        v.x = tile[m4 * 4 + 0][f];
        v.y = tile[m4 * 4 + 1][f];
        v.z = tile[m4 * 4 + 2][f];
        v.w = tile[m4 * 4 + 3][f];
        *reinterpret_cast<float4*>(
            g_ftwT + (size_t)(f0 + f) * MDIM + m0 + m4 * 4) = v;
    }
}

// ---------------------------------------------------------------------------
// Kernel 2: TMA-pipelined streaming scan. One CTA per feature row.
// Double-buffered cp.async.bulk (16 KB tiles); 8 warps scan each tile from
// SMEM; lane 0 of warp w appends nonzero feature indices to list (row, w).
// Deterministic order: tiles ascending, lanes via ballot ascending, bits
// ascending.
// ---------------------------------------------------------------------------
__global__ __launch_bounds__(256) void tma_scan_kernel(
    const float* __restrict__ wf,
    const float* __restrict__ bfeat)
{
    extern __shared__ __align__(16) char smem[];
    const uint32_t sbase = smem_u32(smem);
    const int tid  = threadIdx.x;
    const int w    = tid >> 5;
    const int lane = tid & 31;
    const int row  = blockIdx.x;

    const char* rowp = (const char*)((row < NB)
        ? (wf + (size_t)row * NF)
        : (bfeat + (size_t)(row - NB) * NF));

    // mbarriers after the data buffers: full[s] at +s*16, empty[s] at +s*16+8
    const uint32_t mb = sbase + NBUF * TILE_BYTES;

    if (tid == 0) {
        #pragma unroll
        for (int s = 0; s < NBUF; s++) {
            mbar_init(mb + s * 16 + 0, 1);     // full: tx-based
            mbar_init(mb + s * 16 + 8, 256);   // empty: all threads arrive
        }
        asm volatile("fence.proxy.async.shared::cta;" ::: "memory");
    }
    __syncthreads();

    // prime the pipeline: issue tiles 0 and 1
    if (tid == 0) {
        #pragma unroll
        for (int t = 0; t < NBUF; t++) {
            mbar_expect_tx(mb + t * 16, TILE_BYTES);
            bulk_g2s(sbase + t * TILE_BYTES, rowp + (size_t)t * TILE_BYTES,
                     TILE_BYTES, mb + t * 16);
        }
    }

    int cnt = 0;   // warp-uniform
    int* list = g_list + ((size_t)row * NSEG + w) * SEG_CAP;

    #pragma unroll 1
    for (int t = 0; t < NTILES; t++) {
        const int s = t & 1;
        mbar_wait(mb + s * 16, (t >> 1) & 1);

        // warp w scans uint4 indices w*128 + k*32 + lane, k = 0..3
        const uint32_t baddr = sbase + s * TILE_BYTES + (w * 2048) + lane * 16;
        const uint4 v0 = lds128(baddr + 0 * 512);
        const uint4 v1 = lds128(baddr + 1 * 512);
        const uint4 v2 = lds128(baddr + 2 * 512);
        const uint4 v3 = lds128(baddr + 3 * 512);

        unsigned mask = 0u;
        if (v0.x) mask |= 1u << 0;  if (v0.y) mask |= 1u << 1;
        if (v0.z) mask |= 1u << 2;  if (v0.w) mask |= 1u << 3;
        if (v1.x) mask |= 1u << 4;  if (v1.y) mask |= 1u << 5;
        if (v1.z) mask |= 1u << 6;  if (v1.w) mask |= 1u << 7;
        if (v2.x) mask |= 1u << 8;  if (v2.y) mask |= 1u << 9;
        if (v2.z) mask |= 1u << 10; if (v2.w) mask |= 1u << 11;
        if (v3.x) mask |= 1u << 12; if (v3.y) mask |= 1u << 13;
        if (v3.z) mask |= 1u << 14; if (v3.w) mask |= 1u << 15;

        // values consumed -> this thread is done with the buffer
        mbar_arrive(mb + s * 16 + 8);

        unsigned bal = __ballot_sync(0xffffffffu, mask != 0u);
        if (bal) {
            const int fbase = t * TILE_FLOATS + w * 512;
            do {
                const int src = __ffs(bal) - 1;
                bal &= bal - 1u;
                unsigned sm = __shfl_sync(0xffffffffu, mask, src);
                do {
                    const int b = __ffs(sm) - 1;
                    sm &= sm - 1u;
                    const int f = fbase + (b >> 2) * 128 + src * 4 + (b & 3);
                    if (lane == 0 && cnt < SEG_CAP) list[cnt] = f;
                    cnt++;
                } while (sm);
            } while (bal);
        }

        // producer: refill this buffer with tile t+2 once all 256 arrived
        if (tid == 0 && t + NBUF < NTILES) {
            mbar_wait(mb + s * 16 + 8, (t >> 1) & 1);
            mbar_expect_tx(mb + s * 16, TILE_BYTES);
            bulk_g2s(sbase + s * TILE_BYTES, rowp + (size_t)(t + NBUF) * TILE_BYTES,
                     TILE_BYTES, mb + s * 16);
        }
    }

    if (lane == 0) g_cnt[row * NSEG + w] = (cnt < SEG_CAP) ? cnt : SEG_CAP;
}

// ---------------------------------------------------------------------------
// Kernel 3: gather-accumulate + MLP tail, one CTA per position.
// ---------------------------------------------------------------------------
__device__ __forceinline__ float clamp01(float x) {
    return fminf(fmaxf(x, 0.0f), 1.0f);
}

__global__ __launch_bounds__(256) void gather_mlp_kernel(
    const float* __restrict__ stm,
    const float* __restrict__ ft_b,
    const float* __restrict__ l1_w,
    const float* __restrict__ l1_b,
    const float* __restrict__ l2_w,
    const float* __restrict__ l2_b,
    const float* __restrict__ l3_w,
    const float* __restrict__ l3_b,
    float* __restrict__ out)
{
    const int b   = blockIdx.x;
    const int tid = threadIdx.x;

    __shared__ int   s_list[16][SEG_CAP];  // segs 0..7 white, 8..15 black
    __shared__ int   s_cnt[16];
    __shared__ float s_h[512];
    __shared__ float s_l2x[32];

    // cooperative list load: 16*32 = 512 ints, 2 per thread
    {
        #pragma unroll
        for (int r = 0; r < 2; r++) {
            const int e    = tid + r * 256;
            const int seg  = e >> 5;            // 0..15
            const int slot = e & 31;
            const int row  = (seg < 8) ? b : (NB + b);
            const int wseg = seg & 7;
            s_list[seg][slot] = g_list[((size_t)row * NSEG + wseg) * SEG_CAP + slot];
        }
        if (tid < 16) {
            const int row  = (tid < 8) ? b : (NB + b);
            s_cnt[tid] = g_cnt[row * NSEG + (tid & 7)];
        }
    }
    __syncthreads();

    const float bias = ft_b[tid];
    float accW = bias, accB = bias;
    #pragma unroll
    for (int seg = 0; seg < 16; seg++) {
        const int n = s_cnt[seg];
        float acc = 0.0f;
        int j = 0;
        for (; j + 4 <= n; j += 4) {
            const float a0 = g_ftwT[(size_t)s_list[seg][j + 0] * MDIM + tid];
            const float a1 = g_ftwT[(size_t)s_list[seg][j + 1] * MDIM + tid];
            const float a2 = g_ftwT[(size_t)s_list[seg][j + 2] * MDIM + tid];
            const float a3 = g_ftwT[(size_t)s_list[seg][j + 3] * MDIM + tid];
            acc += a0; acc += a1; acc += a2; acc += a3;
        }
        for (; j < n; j++)
            acc += g_ftwT[(size_t)s_list[seg][j] * MDIM + tid];
        if (seg < 8) accW += acc; else accB += acc;
    }

    const float s  = stm[b];
    s_h[tid]       = clamp01(s * accW + (1.0f - s) * accB);
    s_h[256 + tid] = clamp01(s * accB + (1.0f - s) * accW);
    __syncthreads();

    // L1: 512 -> 32. Output n = tid>>3; 8 threads per output.
    {
        const int n   = tid >> 3;
        const int seg = tid & 7;
        const float4* wrow = reinterpret_cast<const float4*>(l1_w + n * 512 + seg * 64);
        const float4* hv   = reinterpret_cast<const float4*>(s_h) + seg * 16;
        float psum = 0.0f;
        #pragma unroll
        for (int i = 0; i < 16; i++) {
            const float4 a = wrow[i];
            const float4 x = hv[i];
            psum += a.x * x.x;
            psum += a.y * x.y;
            psum += a.z * x.z;
            psum += a.w * x.w;
        }
        psum += __shfl_down_sync(0xffffffffu, psum, 4);
        psum += __shfl_down_sync(0xffffffffu, psum, 2);
        psum += __shfl_down_sync(0xffffffffu, psum, 1);
        if (seg == 0) s_l2x[n] = clamp01(psum + l1_b[n]);
    }
    __syncthreads();

    // L2 (32->32), L3 (32->1), eval scaling. Warp 0 only.
    if (tid < 32) {
        float q = l2_b[tid];
        #pragma unroll
        for (int k = 0; k < 32; k++) q += l2_w[tid * 32 + k] * s_l2x[k];
        const float l3x = clamp01(q);
        float t = l3x * l3_w[tid];
        #pragma unroll
        for (int off = 16; off > 0; off >>= 1)
            t += __shfl_down_sync(0xffffffffu, t, off);
        if (tid == 0) {
            const float ev = clamp01(t + l3_b[0]);
            out[b] = (ev - 0.5f) * 2.0f * 10000.0f;
        }
    }
}

// ---------------------------------------------------------------------------
// Launch
// ---------------------------------------------------------------------------
extern "C" void kernel_launch(void* const* d_in, const int* in_sizes, int n_in,
                              void* d_out, int out_size)
{
    const float* wf    = (const float*)d_in[0];
    const float* bfeat = (const float*)d_in[1];
    const float* stm   = (const float*)d_in[2];
    const float* ft_w  = (const float*)d_in[3];
    const float* ft_b  = (const float*)d_in[4];
    const float* l1_w  = (const float*)d_in[5];
    const float* l1_b  = (const float*)d_in[6];
    const float* l2_w  = (const float*)d_in[7];
    const float* l2_b  = (const float*)d_in[8];
    const float* l3_w  = (const float*)d_in[9];
    const float* l3_b  = (const float*)d_in[10];
    float* out = (float*)d_out;

    // 1) Transpose ft_w -> g_ftwT (gather table)
    dim3 tgrid(NF / 32, MDIM / 32);
    transpose_ftw_kernel<<<tgrid, 256>>>(ft_w);

    // 2) TMA-pipelined scan: one CTA per row
    const int smem_bytes = NBUF * TILE_BYTES + NBUF * 16;   // 32800 < 48KB default
    tma_scan_kernel<<<ROWS, 256, smem_bytes>>>(wf, bfeat);

    // 3) Gather + MLP tail, one CTA per position
    gather_mlp_kernel<<<NB, 256>>>(stm, ft_b, l1_w, l1_b, l2_w, l2_b,
                                   l3_w, l3_b, out);
}

// round 7
// speedup vs baseline: 1.1375x; 1.1375x over previous
#include <cuda_runtime.h>
#include <cstdint>

#define NF       40960
#define MDIM     256
#define NB       2048
#define ROWS     (2*NB)          // 4096 feature rows (white then black)
#define WPR      1280            // bitmap words per row (NF/32)
#define CHUNK_V4 1280            // float4s per warp chunk (NF/4/8)
#define NBATCH   5               // batches of 8 float4/lane per warp chunk
#define CAP      192             // per-color index list capacity

// Transposed feature-transformer weights: ft_wT[f][m], 40960 x 256 fp32 = 41.9 MB
__device__ float g_ftwT[NF * MDIM];
// Nonzero bitmap: 4096 rows x 1280 words = 20 MB
__device__ unsigned g_bitmap[ROWS * WPR];

// ---------------------------------------------------------------------------
// Kernel 1: tiled transpose ft_w [256, 40960] -> g_ftwT [40960, 256]
// ---------------------------------------------------------------------------
__global__ __launch_bounds__(256) void transpose_ftw_kernel(const float* __restrict__ ft_w) {
    __shared__ float tile[32][33];
    const int f0 = blockIdx.x * 32;
    const int m0 = blockIdx.y * 32;
    const int t  = threadIdx.x;
    {
        const int m = t >> 3;
        const int q = t & 7;
        const float4 v = *reinterpret_cast<const float4*>(
            ft_w + (size_t)(m0 + m) * NF + f0 + q * 4);
        tile[m][q * 4 + 0] = v.x;
        tile[m][q * 4 + 1] = v.y;
        tile[m][q * 4 + 2] = v.z;
        tile[m][q * 4 + 3] = v.w;
    }
    __syncthreads();
    {
        const int f  = t >> 3;
        const int m4 = t & 7;
        float4 v;
        v.x = tile[m4 * 4 + 0][f];
        v.y = tile[m4 * 4 + 1][f];
        v.z = tile[m4 * 4 + 2][f];
        v.w = tile[m4 * 4 + 3][f];
        *reinterpret_cast<float4*>(
            g_ftwT + (size_t)(f0 + f) * MDIM + m0 + m4 * 4) = v;
    }
}

// ---------------------------------------------------------------------------
// Kernel 2: ballot-free streaming scan -> bitmap.
// One warp per (row, eighth). Lane-local masks, one coalesced STG.32 per
// 4KB batch. No cross-lane ops, no divergent branches: warps free-run.
// Word layout: w = eighth*160 + t*32 + lane; bit (u*4+c) = component c of
// float4 (t*256 + u*32 + lane) within the eighth-chunk.
// ---------------------------------------------------------------------------
__global__ __launch_bounds__(256) void scan_bitmap_kernel(
    const float* __restrict__ wf,
    const float* __restrict__ bfeat)
{
    const int gw     = (blockIdx.x * blockDim.x + threadIdx.x) >> 5; // 0..32767
    const int lane   = threadIdx.x & 31;
    const int row    = gw >> 3;
    const int eighth = gw & 7;

    const float* rowp = (row < NB) ? (wf + (size_t)row * NF)
                                   : (bfeat + (size_t)(row - NB) * NF);
    const uint4* p = reinterpret_cast<const uint4*>(rowp) + eighth * CHUNK_V4;
    unsigned* wout = g_bitmap + (size_t)row * WPR + eighth * 160;

    uint4 v[8];
    #pragma unroll
    for (int u = 0; u < 8; u++)
        v[u] = __ldcs(&p[u * 32 + lane]);

    #pragma unroll
    for (int t = 0; t < NBATCH; t++) {
        uint4 nv[8];
        if (t + 1 < NBATCH) {
            #pragma unroll
            for (int u = 0; u < 8; u++)
                nv[u] = __ldcs(&p[(t + 1) * 256 + u * 32 + lane]);
        }
        unsigned mask = 0u;
        #pragma unroll
        for (int u = 0; u < 8; u++) {
            if (v[u].x) mask |= 1u << (u * 4 + 0);
            if (v[u].y) mask |= 1u << (u * 4 + 1);
            if (v[u].z) mask |= 1u << (u * 4 + 2);
            if (v[u].w) mask |= 1u << (u * 4 + 3);
        }
        wout[t * 32 + lane] = mask;
        if (t + 1 < NBATCH) {
            #pragma unroll
            for (int u = 0; u < 8; u++) v[u] = nv[u];
        }
    }
}

// ---------------------------------------------------------------------------
// Kernel 3: bitmap decode (deterministic CTA compaction) + gather + MLP tail.
// One CTA (256 threads) per position.
// ---------------------------------------------------------------------------
__device__ __forceinline__ float clamp01(float x) {
    return fminf(fmaxf(x, 0.0f), 1.0f);
}

// decode word index w (0..1279) + bit j -> feature index
__device__ __forceinline__ int decode_f(int w, int j) {
    const int eighth = w / 160;
    const int r      = w - eighth * 160;
    const int t      = r >> 5;
    const int l      = r & 31;
    return eighth * 5120 + t * 1024 + (j >> 2) * 128 + l * 4 + (j & 3);
}

__global__ __launch_bounds__(256) void gather_mlp_kernel(
    const float* __restrict__ stm,
    const float* __restrict__ ft_b,
    const float* __restrict__ l1_w,
    const float* __restrict__ l1_b,
    const float* __restrict__ l2_w,
    const float* __restrict__ l2_b,
    const float* __restrict__ l3_w,
    const float* __restrict__ l3_b,
    float* __restrict__ out)
{
    const int b    = blockIdx.x;
    const int tid  = threadIdx.x;
    const int lane = tid & 31;
    const int wid  = tid >> 5;

    // float4-accessed arrays first + explicitly 16B aligned (round-6 bug:
    // s_h landed on a non-16B offset and float4 lds trapped).
    __shared__ __align__(16) float s_h[512];
    __shared__ __align__(16) int   s_idxW[CAP];
    __shared__ __align__(16) int   s_idxB[CAP];
    __shared__ float s_l2x[32];
    __shared__ int   s_wsum[8], s_bsum[8];
    __shared__ int   s_nW, s_nB;

    // load bitmap words: thread tid owns words w = k*256 + tid, k = 0..4
    unsigned ww[5], bw[5];
    const unsigned* wbm = g_bitmap + (size_t)b * WPR;
    const unsigned* bbm = g_bitmap + (size_t)(NB + b) * WPR;
    #pragma unroll
    for (int k = 0; k < 5; k++) {
        ww[k] = wbm[k * 256 + tid];
        bw[k] = bbm[k * 256 + tid];
    }

    int cw = 0, cb = 0;
    #pragma unroll
    for (int k = 0; k < 5; k++) {
        cw += __popc(ww[k]);
        cb += __popc(bw[k]);
    }

    // CTA exclusive prefix sums (deterministic thread order)
    int wexc = cw, bexc = cb;
    #pragma unroll
    for (int d = 1; d < 32; d <<= 1) {
        const int nw = __shfl_up_sync(0xffffffffu, wexc, d);
        const int nb = __shfl_up_sync(0xffffffffu, bexc, d);
        if (lane >= d) { wexc += nw; bexc += nb; }
    }
    wexc -= cw; bexc -= cb;   // inclusive -> exclusive
    if (lane == 31) {
        s_wsum[wid] = wexc + cw;
        s_bsum[wid] = bexc + cb;
    }
    __syncthreads();
    if (tid == 0) {
        int aw = 0, ab = 0;
        #pragma unroll
        for (int i = 0; i < 8; i++) {
            const int tw = s_wsum[i]; s_wsum[i] = aw; aw += tw;
            const int tb = s_bsum[i]; s_bsum[i] = ab; ab += tb;
        }
        s_nW = (aw < CAP) ? aw : CAP;
        s_nB = (ab < CAP) ? ab : CAP;
    }
    __syncthreads();

    // deposit indices in deterministic (thread, word, bit) order
    {
        int ow = s_wsum[wid] + wexc;
        int ob = s_bsum[wid] + bexc;
        #pragma unroll
        for (int k = 0; k < 5; k++) {
            unsigned m = ww[k];
            const int w = k * 256 + tid;
            while (m) {
                const int j = __ffs(m) - 1;
                m &= m - 1u;
                if (ow < CAP) s_idxW[ow] = decode_f(w, j);
                ow++;
            }
            m = bw[k];
            while (m) {
                const int j = __ffs(m) - 1;
                m &= m - 1u;
                if (ob < CAP) s_idxB[ob] = decode_f(w, j);
                ob++;
            }
        }
    }
    __syncthreads();

    // gather-accumulate: thread tid owns output m = tid
    const float bias = ft_b[tid];
    float accW = bias, accB = bias;
    {
        const int nW = s_nW;
        int j = 0;
        for (; j + 4 <= nW; j += 4) {
            const float a0 = g_ftwT[(size_t)s_idxW[j + 0] * MDIM + tid];
            const float a1 = g_ftwT[(size_t)s_idxW[j + 1] * MDIM + tid];
            const float a2 = g_ftwT[(size_t)s_idxW[j + 2] * MDIM + tid];
            const float a3 = g_ftwT[(size_t)s_idxW[j + 3] * MDIM + tid];
            accW += a0; accW += a1; accW += a2; accW += a3;
        }
        for (; j < nW; j++) accW += g_ftwT[(size_t)s_idxW[j] * MDIM + tid];

        const int nB = s_nB;
        j = 0;
        for (; j + 4 <= nB; j += 4) {
            const float a0 = g_ftwT[(size_t)s_idxB[j + 0] * MDIM + tid];
            const float a1 = g_ftwT[(size_t)s_idxB[j + 1] * MDIM + tid];
            const float a2 = g_ftwT[(size_t)s_idxB[j + 2] * MDIM + tid];
            const float a3 = g_ftwT[(size_t)s_idxB[j + 3] * MDIM + tid];
            accB += a0; accB += a1; accB += a2; accB += a3;
        }
        for (; j < nB; j++) accB += g_ftwT[(size_t)s_idxB[j] * MDIM + tid];
    }

    // stm blend + clip
    const float s  = stm[b];
    s_h[tid]       = clamp01(s * accW + (1.0f - s) * accB);
    s_h[256 + tid] = clamp01(s * accB + (1.0f - s) * accW);
    __syncthreads();

    // L1: 512 -> 32. Output n = tid>>3; 8 threads per output.
    {
        const int n   = tid >> 3;
        const int seg = tid & 7;
        const float4* wrow = reinterpret_cast<const float4*>(l1_w + n * 512 + seg * 64);
        const float4* hv   = reinterpret_cast<const float4*>(s_h) + seg * 16;
        float psum = 0.0f;
        #pragma unroll
        for (int i = 0; i < 16; i++) {
            const float4 a = wrow[i];
            const float4 x = hv[i];
            psum += a.x * x.x;
            psum += a.y * x.y;
            psum += a.z * x.z;
            psum += a.w * x.w;
        }
        psum += __shfl_down_sync(0xffffffffu, psum, 4);
        psum += __shfl_down_sync(0xffffffffu, psum, 2);
        psum += __shfl_down_sync(0xffffffffu, psum, 1);
        if (seg == 0) s_l2x[n] = clamp01(psum + l1_b[n]);
    }
    __syncthreads();

    // L2 (32->32), L3 (32->1), eval scaling. Warp 0 only.
    if (tid < 32) {
        float q = l2_b[tid];
        #pragma unroll
        for (int k = 0; k < 32; k++) q += l2_w[tid * 32 + k] * s_l2x[k];
        const float l3x = clamp01(q);
        float t = l3x * l3_w[tid];
        #pragma unroll
        for (int off = 16; off > 0; off >>= 1)
            t += __shfl_down_sync(0xffffffffu, t, off);
        if (tid == 0) {
            const float ev = clamp01(t + l3_b[0]);
            out[b] = (ev - 0.5f) * 2.0f * 10000.0f;
        }
    }
}

// ---------------------------------------------------------------------------
// Launch
// ---------------------------------------------------------------------------
extern "C" void kernel_launch(void* const* d_in, const int* in_sizes, int n_in,
                              void* d_out, int out_size)
{
    const float* wf    = (const float*)d_in[0];
    const float* bfeat = (const float*)d_in[1];
    const float* stm   = (const float*)d_in[2];
    const float* ft_w  = (const float*)d_in[3];
    const float* ft_b  = (const float*)d_in[4];
    const float* l1_w  = (const float*)d_in[5];
    const float* l1_b  = (const float*)d_in[6];
    const float* l2_w  = (const float*)d_in[7];
    const float* l2_b  = (const float*)d_in[8];
    const float* l3_w  = (const float*)d_in[9];
    const float* l3_b  = (const float*)d_in[10];
    float* out = (float*)d_out;

    // 1) Transpose ft_w -> g_ftwT (gather table)
    dim3 tgrid(NF / 32, MDIM / 32);
    transpose_ftw_kernel<<<tgrid, 256>>>(ft_w);

    // 2) Ballot-free streaming scan -> bitmap (32768 warps)
    scan_bitmap_kernel<<<(ROWS * 8) / 8, 256>>>(wf, bfeat);

    // 3) Decode + gather + MLP tail, one CTA per position
    gather_mlp_kernel<<<NB, 256>>>(stm, ft_b, l1_w, l1_b, l2_w, l2_b,
                                   l3_w, l3_b, out);
}

// round 8
// speedup vs baseline: 1.1727x; 1.0310x over previous
#include <cuda_runtime.h>
#include <cstdint>

#define NF       40960
#define MDIM     256
#define NB       2048
#define ROWS     (2*NB)          // 4096 feature rows (white then black)
#define WPR      1280            // bitmap words per row (NF/32)
#define CHUNK_V4 1280            // float4s per warp chunk (NF/4/8)
#define CAP      192             // per-color index list capacity

#define SCAN_CTAS 4096           // 8 warps per CTA, warp per (row, eighth)
#define TR_X      (NF/32)        // 1280
#define TR_Y      (MDIM/32)      // 8
#define TR_CTAS   (TR_X*TR_Y)    // 10240

// Transposed feature-transformer weights: ft_wT[f][m], 40960 x 256 fp32 = 41.9 MB
__device__ float g_ftwT[NF * MDIM];
// Nonzero bitmap: 4096 rows x 1280 words = 20 MB
__device__ unsigned g_bitmap[ROWS * WPR];

// ---------------------------------------------------------------------------
// Kernel 1: fused [streaming scan -> bitmap] + [ft_w transpose].
// Independent work items in one grid: blockIdx < SCAN_CTAS -> scan CTA
// (low bids launch first = long pole), else transpose tile CTA (backfills).
//
// Scan: one warp per (row, eighth). NO manual prefetch: only 4 uint4 live
// (16 regs) so ptxas cannot spill; independent load groups still overlap.
// Word layout: w = eighth*160 + t*32 + lane; bit (g*16 + u*4 + c) =
// component c of float4 (t*256 + (g*4+u)*32 + lane) of the chunk.
// ---------------------------------------------------------------------------
__global__ __launch_bounds__(256) void scan_transpose_kernel(
    const float* __restrict__ wf,
    const float* __restrict__ bfeat,
    const float* __restrict__ ft_w)
{
    __shared__ float tile[32][33];

    if (blockIdx.x < SCAN_CTAS) {
        // ---------------- scan branch ----------------
        const int gw     = (blockIdx.x << 3) | (threadIdx.x >> 5);  // 0..32767
        const int lane   = threadIdx.x & 31;
        const int row    = gw >> 3;
        const int eighth = gw & 7;

        const float* rowp = (row < NB) ? (wf + (size_t)row * NF)
                                       : (bfeat + (size_t)(row - NB) * NF);
        const uint4* p = reinterpret_cast<const uint4*>(rowp) + eighth * CHUNK_V4;
        unsigned* wout = g_bitmap + (size_t)row * WPR + eighth * 160;

        #pragma unroll
        for (int t = 0; t < 5; t++) {
            unsigned mask = 0u;
            #pragma unroll
            for (int g = 0; g < 2; g++) {
                uint4 v0 = __ldcs(&p[t * 256 + (g * 4 + 0) * 32 + lane]);
                uint4 v1 = __ldcs(&p[t * 256 + (g * 4 + 1) * 32 + lane]);
                uint4 v2 = __ldcs(&p[t * 256 + (g * 4 + 2) * 32 + lane]);
                uint4 v3 = __ldcs(&p[t * 256 + (g * 4 + 3) * 32 + lane]);
                const int s = g * 16;
                if (v0.x) mask |= 1u << (s + 0);  if (v0.y) mask |= 1u << (s + 1);
                if (v0.z) mask |= 1u << (s + 2);  if (v0.w) mask |= 1u << (s + 3);
                if (v1.x) mask |= 1u << (s + 4);  if (v1.y) mask |= 1u << (s + 5);
                if (v1.z) mask |= 1u << (s + 6);  if (v1.w) mask |= 1u << (s + 7);
                if (v2.x) mask |= 1u << (s + 8);  if (v2.y) mask |= 1u << (s + 9);
                if (v2.z) mask |= 1u << (s + 10); if (v2.w) mask |= 1u << (s + 11);
                if (v3.x) mask |= 1u << (s + 12); if (v3.y) mask |= 1u << (s + 13);
                if (v3.z) mask |= 1u << (s + 14); if (v3.w) mask |= 1u << (s + 15);
            }
            wout[t * 32 + lane] = mask;
        }
    } else {
        // ---------------- transpose branch ----------------
        const int tb = blockIdx.x - SCAN_CTAS;
        const int f0 = (tb % TR_X) * 32;
        const int m0 = (tb / TR_X) * 32;
        const int t  = threadIdx.x;
        {
            const int m = t >> 3;
            const int q = t & 7;
            const float4 v = *reinterpret_cast<const float4*>(
                ft_w + (size_t)(m0 + m) * NF + f0 + q * 4);
            tile[m][q * 4 + 0] = v.x;
            tile[m][q * 4 + 1] = v.y;
            tile[m][q * 4 + 2] = v.z;
            tile[m][q * 4 + 3] = v.w;
        }
        __syncthreads();
        {
            const int f  = t >> 3;
            const int m4 = t & 7;
            float4 v;
            v.x = tile[m4 * 4 + 0][f];
            v.y = tile[m4 * 4 + 1][f];
            v.z = tile[m4 * 4 + 2][f];
            v.w = tile[m4 * 4 + 3][f];
            *reinterpret_cast<float4*>(
                g_ftwT + (size_t)(f0 + f) * MDIM + m0 + m4 * 4) = v;
        }
    }
}

// ---------------------------------------------------------------------------
// Kernel 2: bitmap decode (deterministic CTA compaction) + gather + MLP tail.
// One CTA (256 threads) per position.
// ---------------------------------------------------------------------------
__device__ __forceinline__ float clamp01(float x) {
    return fminf(fmaxf(x, 0.0f), 1.0f);
}

// decode word index w (0..1279) + bit j -> feature index
__device__ __forceinline__ int decode_f(int w, int j) {
    const int eighth = w / 160;
    const int r      = w - eighth * 160;
    const int t      = r >> 5;
    const int l      = r & 31;
    return eighth * 5120 + t * 1024 + (j >> 2) * 128 + l * 4 + (j & 3);
}

__global__ __launch_bounds__(256) void gather_mlp_kernel(
    const float* __restrict__ stm,
    const float* __restrict__ ft_b,
    const float* __restrict__ l1_w,
    const float* __restrict__ l1_b,
    const float* __restrict__ l2_w,
    const float* __restrict__ l2_b,
    const float* __restrict__ l3_w,
    const float* __restrict__ l3_b,
    float* __restrict__ out)
{
    const int b    = blockIdx.x;
    const int tid  = threadIdx.x;
    const int lane = tid & 31;
    const int wid  = tid >> 5;

    __shared__ __align__(16) float s_h[512];
    __shared__ __align__(16) int   s_idxW[CAP];
    __shared__ __align__(16) int   s_idxB[CAP];
    __shared__ float s_l2x[32];
    __shared__ int   s_wsum[8], s_bsum[8];
    __shared__ int   s_nW, s_nB;

    // load bitmap words: thread tid owns words w = k*256 + tid, k = 0..4
    unsigned ww[5], bw[5];
    const unsigned* wbm = g_bitmap + (size_t)b * WPR;
    const unsigned* bbm = g_bitmap + (size_t)(NB + b) * WPR;
    #pragma unroll
    for (int k = 0; k < 5; k++) {
        ww[k] = wbm[k * 256 + tid];
        bw[k] = bbm[k * 256 + tid];
    }

    int cw = 0, cb = 0;
    #pragma unroll
    for (int k = 0; k < 5; k++) {
        cw += __popc(ww[k]);
        cb += __popc(bw[k]);
    }

    // CTA exclusive prefix sums (deterministic thread order)
    int wexc = cw, bexc = cb;
    #pragma unroll
    for (int d = 1; d < 32; d <<= 1) {
        const int nw = __shfl_up_sync(0xffffffffu, wexc, d);
        const int nb = __shfl_up_sync(0xffffffffu, bexc, d);
        if (lane >= d) { wexc += nw; bexc += nb; }
    }
    wexc -= cw; bexc -= cb;
    if (lane == 31) {
        s_wsum[wid] = wexc + cw;
        s_bsum[wid] = bexc + cb;
    }
    __syncthreads();
    if (tid == 0) {
        int aw = 0, ab = 0;
        #pragma unroll
        for (int i = 0; i < 8; i++) {
            const int tw = s_wsum[i]; s_wsum[i] = aw; aw += tw;
            const int tb = s_bsum[i]; s_bsum[i] = ab; ab += tb;
        }
        s_nW = (aw < CAP) ? aw : CAP;
        s_nB = (ab < CAP) ? ab : CAP;
    }
    __syncthreads();

    // deposit indices in deterministic (thread, word, bit) order
    {
        int ow = s_wsum[wid] + wexc;
        int ob = s_bsum[wid] + bexc;
        #pragma unroll
        for (int k = 0; k < 5; k++) {
            unsigned m = ww[k];
            const int w = k * 256 + tid;
            while (m) {
                const int j = __ffs(m) - 1;
                m &= m - 1u;
                if (ow < CAP) s_idxW[ow] = decode_f(w, j);
                ow++;
            }
            m = bw[k];
            while (m) {
                const int j = __ffs(m) - 1;
                m &= m - 1u;
                if (ob < CAP) s_idxB[ob] = decode_f(w, j);
                ob++;
            }
        }
    }
    __syncthreads();

    // gather-accumulate: thread tid owns output m = tid
    const float bias = ft_b[tid];
    float accW = bias, accB = bias;
    {
        const int nW = s_nW;
        int j = 0;
        for (; j + 4 <= nW; j += 4) {
            const float a0 = g_ftwT[(size_t)s_idxW[j + 0] * MDIM + tid];
            const float a1 = g_ftwT[(size_t)s_idxW[j + 1] * MDIM + tid];
            const float a2 = g_ftwT[(size_t)s_idxW[j + 2] * MDIM + tid];
            const float a3 = g_ftwT[(size_t)s_idxW[j + 3] * MDIM + tid];
            accW += a0; accW += a1; accW += a2; accW += a3;
        }
        for (; j < nW; j++) accW += g_ftwT[(size_t)s_idxW[j] * MDIM + tid];

        const int nB = s_nB;
        j = 0;
        for (; j + 4 <= nB; j += 4) {
            const float a0 = g_ftwT[(size_t)s_idxB[j + 0] * MDIM + tid];
            const float a1 = g_ftwT[(size_t)s_idxB[j + 1] * MDIM + tid];
            const float a2 = g_ftwT[(size_t)s_idxB[j + 2] * MDIM + tid];
            const float a3 = g_ftwT[(size_t)s_idxB[j + 3] * MDIM + tid];
            accB += a0; accB += a1; accB += a2; accB += a3;
        }
        for (; j < nB; j++) accB += g_ftwT[(size_t)s_idxB[j] * MDIM + tid];
    }

    // stm blend + clip
    const float s  = stm[b];
    s_h[tid]       = clamp01(s * accW + (1.0f - s) * accB);
    s_h[256 + tid] = clamp01(s * accB + (1.0f - s) * accW);
    __syncthreads();

    // L1: 512 -> 32. Output n = tid>>3; 8 threads per output.
    {
        const int n   = tid >> 3;
        const int seg = tid & 7;
        const float4* wrow = reinterpret_cast<const float4*>(l1_w + n * 512 + seg * 64);
        const float4* hv   = reinterpret_cast<const float4*>(s_h) + seg * 16;
        float psum = 0.0f;
        #pragma unroll
        for (int i = 0; i < 16; i++) {
            const float4 a = wrow[i];
            const float4 x = hv[i];
            psum += a.x * x.x;
            psum += a.y * x.y;
            psum += a.z * x.z;
            psum += a.w * x.w;
        }
        psum += __shfl_down_sync(0xffffffffu, psum, 4);
        psum += __shfl_down_sync(0xffffffffu, psum, 2);
        psum += __shfl_down_sync(0xffffffffu, psum, 1);
        if (seg == 0) s_l2x[n] = clamp01(psum + l1_b[n]);
    }
    __syncthreads();

    // L2 (32->32), L3 (32->1), eval scaling. Warp 0 only.
    if (tid < 32) {
        float q = l2_b[tid];
        #pragma unroll
        for (int k = 0; k < 32; k++) q += l2_w[tid * 32 + k] * s_l2x[k];
        const float l3x = clamp01(q);
        float t = l3x * l3_w[tid];
        #pragma unroll
        for (int off = 16; off > 0; off >>= 1)
            t += __shfl_down_sync(0xffffffffu, t, off);
        if (tid == 0) {
            const float ev = clamp01(t + l3_b[0]);
            out[b] = (ev - 0.5f) * 2.0f * 10000.0f;
        }
    }
}

// ---------------------------------------------------------------------------
// Launch
// ---------------------------------------------------------------------------
extern "C" void kernel_launch(void* const* d_in, const int* in_sizes, int n_in,
                              void* d_out, int out_size)
{
    const float* wf    = (const float*)d_in[0];
    const float* bfeat = (const float*)d_in[1];
    const float* stm   = (const float*)d_in[2];
    const float* ft_w  = (const float*)d_in[3];
    const float* ft_b  = (const float*)d_in[4];
    const float* l1_w  = (const float*)d_in[5];
    const float* l1_b  = (const float*)d_in[6];
    const float* l2_w  = (const float*)d_in[7];
    const float* l2_b  = (const float*)d_in[8];
    const float* l3_w  = (const float*)d_in[9];
    const float* l3_b  = (const float*)d_in[10];
    float* out = (float*)d_out;

    // 1) Fused scan (bitmap) + transpose in one grid
    scan_transpose_kernel<<<SCAN_CTAS + TR_CTAS, 256>>>(wf, bfeat, ft_w);

    // 2) Decode + gather + MLP tail, one CTA per position
    gather_mlp_kernel<<<NB, 256>>>(stm, ft_b, l1_w, l1_b, l2_w, l2_b,
                                   l3_w, l3_b, out);
}

// round 9
// speedup vs baseline: 1.6511x; 1.4079x over previous
#include <cuda_runtime.h>
#include <cstdint>

#define NF       40960
#define MDIM     256
#define NB       2048
#define ROWS     (2*NB)          // 4096 feature rows (white then black)
#define WPR      1280            // bitmap words per row (NF/32)
#define CHUNK_V4 1280            // float4s per warp chunk (NF/4/8)
#define CAP      192             // per-color index list capacity

#define SCAN_CTAS 4096           // 8 warps per CTA, warp per (row, eighth)
#define TR_X      (NF/32)        // 1280
#define TR_Y      (MDIM/32)      // 8
#define TR_CTAS   (TR_X*TR_Y)    // 10240

// Transposed feature-transformer weights: ft_wT[f][m], 40960 x 256 fp32 = 41.9 MB
__device__ float g_ftwT[NF * MDIM];
// Nonzero bitmap: 4096 rows x 1280 words = 20 MB
__device__ unsigned g_bitmap[ROWS * WPR];

// ---------------------------------------------------------------------------
// Kernel 1: fused [streaming scan -> bitmap] + [ft_w transpose].
// (unchanged from round 8 — runs at ~107us, near the 671MB stream floor)
// ---------------------------------------------------------------------------
__global__ __launch_bounds__(256) void scan_transpose_kernel(
    const float* __restrict__ wf,
    const float* __restrict__ bfeat,
    const float* __restrict__ ft_w)
{
    __shared__ float tile[32][33];

    if (blockIdx.x < SCAN_CTAS) {
        const int gw     = (blockIdx.x << 3) | (threadIdx.x >> 5);
        const int lane   = threadIdx.x & 31;
        const int row    = gw >> 3;
        const int eighth = gw & 7;

        const float* rowp = (row < NB) ? (wf + (size_t)row * NF)
                                       : (bfeat + (size_t)(row - NB) * NF);
        const uint4* p = reinterpret_cast<const uint4*>(rowp) + eighth * CHUNK_V4;
        unsigned* wout = g_bitmap + (size_t)row * WPR + eighth * 160;

        #pragma unroll
        for (int t = 0; t < 5; t++) {
            unsigned mask = 0u;
            #pragma unroll
            for (int g = 0; g < 2; g++) {
                uint4 v0 = __ldcs(&p[t * 256 + (g * 4 + 0) * 32 + lane]);
                uint4 v1 = __ldcs(&p[t * 256 + (g * 4 + 1) * 32 + lane]);
                uint4 v2 = __ldcs(&p[t * 256 + (g * 4 + 2) * 32 + lane]);
                uint4 v3 = __ldcs(&p[t * 256 + (g * 4 + 3) * 32 + lane]);
                const int s = g * 16;
                if (v0.x) mask |= 1u << (s + 0);  if (v0.y) mask |= 1u << (s + 1);
                if (v0.z) mask |= 1u << (s + 2);  if (v0.w) mask |= 1u << (s + 3);
                if (v1.x) mask |= 1u << (s + 4);  if (v1.y) mask |= 1u << (s + 5);
                if (v1.z) mask |= 1u << (s + 6);  if (v1.w) mask |= 1u << (s + 7);
                if (v2.x) mask |= 1u << (s + 8);  if (v2.y) mask |= 1u << (s + 9);
                if (v2.z) mask |= 1u << (s + 10); if (v2.w) mask |= 1u << (s + 11);
                if (v3.x) mask |= 1u << (s + 12); if (v3.y) mask |= 1u << (s + 13);
                if (v3.z) mask |= 1u << (s + 14); if (v3.w) mask |= 1u << (s + 15);
            }
            wout[t * 32 + lane] = mask;
        }
    } else {
        const int tb = blockIdx.x - SCAN_CTAS;
        const int f0 = (tb % TR_X) * 32;
        const int m0 = (tb / TR_X) * 32;
        const int t  = threadIdx.x;
        {
            const int m = t >> 3;
            const int q = t & 7;
            const float4 v = *reinterpret_cast<const float4*>(
                ft_w + (size_t)(m0 + m) * NF + f0 + q * 4);
            tile[m][q * 4 + 0] = v.x;
            tile[m][q * 4 + 1] = v.y;
            tile[m][q * 4 + 2] = v.z;
            tile[m][q * 4 + 3] = v.w;
        }
        __syncthreads();
        {
            const int f  = t >> 3;
            const int m4 = t & 7;
            float4 v;
            v.x = tile[m4 * 4 + 0][f];
            v.y = tile[m4 * 4 + 1][f];
            v.z = tile[m4 * 4 + 2][f];
            v.w = tile[m4 * 4 + 3][f];
            *reinterpret_cast<float4*>(
                g_ftwT + (size_t)(f0 + f) * MDIM + m0 + m4 * 4) = v;
        }
    }
}

// ---------------------------------------------------------------------------
// Kernel 2: bitmap decode + gather + MLP tail, wavefront-optimized.
// ---------------------------------------------------------------------------
__device__ __forceinline__ float clamp01(float x) {
    return fminf(fmaxf(x, 0.0f), 1.0f);
}

__device__ __forceinline__ int decode_f(int w, int j) {
    const int eighth = w / 160;
    const int r      = w - eighth * 160;
    const int t      = r >> 5;
    const int l      = r & 31;
    return eighth * 5120 + t * 1024 + (j >> 2) * 128 + l * 4 + (j & 3);
}

__global__ __launch_bounds__(256) void gather_mlp_kernel(
    const float* __restrict__ stm,
    const float* __restrict__ ft_b,
    const float* __restrict__ l1_w,
    const float* __restrict__ l1_b,
    const float* __restrict__ l2_w,
    const float* __restrict__ l2_b,
    const float* __restrict__ l3_w,
    const float* __restrict__ l3_b,
    float* __restrict__ out)
{
    const int b    = blockIdx.x;
    const int tid  = threadIdx.x;
    const int lane = tid & 31;
    const int wid  = tid >> 5;

    __shared__ __align__(16) float s_h[512];
    __shared__ __align__(16) int   s_idxW[CAP];
    __shared__ __align__(16) int   s_idxB[CAP];
    __shared__ float s_l2w[32 * 33];   // padded: bank-conflict-free row reads
    __shared__ float s_l2x[32];
    __shared__ int   s_wsum[8], s_bsum[8];
    __shared__ int   s_nW, s_nB;

    // stage l2_w into padded smem (coalesced; overlaps with bitmap latency)
    #pragma unroll
    for (int i = tid; i < 1024; i += 256)
        s_l2w[(i >> 5) * 33 + (i & 31)] = l2_w[i];

    // load bitmap words: thread tid owns words w = k*256 + tid, k = 0..4
    unsigned ww[5], bw[5];
    const unsigned* wbm = g_bitmap + (size_t)b * WPR;
    const unsigned* bbm = g_bitmap + (size_t)(NB + b) * WPR;
    #pragma unroll
    for (int k = 0; k < 5; k++) {
        ww[k] = wbm[k * 256 + tid];
        bw[k] = bbm[k * 256 + tid];
    }

    int cw = 0, cb = 0;
    #pragma unroll
    for (int k = 0; k < 5; k++) {
        cw += __popc(ww[k]);
        cb += __popc(bw[k]);
    }

    // CTA exclusive prefix sums (deterministic thread order)
    int wexc = cw, bexc = cb;
    #pragma unroll
    for (int d = 1; d < 32; d <<= 1) {
        const int nw = __shfl_up_sync(0xffffffffu, wexc, d);
        const int nb = __shfl_up_sync(0xffffffffu, bexc, d);
        if (lane >= d) { wexc += nw; bexc += nb; }
    }
    wexc -= cw; bexc -= cb;
    if (lane == 31) {
        s_wsum[wid] = wexc + cw;
        s_bsum[wid] = bexc + cb;
    }
    __syncthreads();
    if (tid == 0) {
        int aw = 0, ab = 0;
        #pragma unroll
        for (int i = 0; i < 8; i++) {
            const int tw = s_wsum[i]; s_wsum[i] = aw; aw += tw;
            const int tb = s_bsum[i]; s_bsum[i] = ab; ab += tb;
        }
        s_nW = (aw < CAP) ? aw : CAP;
        s_nB = (ab < CAP) ? ab : CAP;
    }
    __syncthreads();

    // deposit indices in deterministic (thread, word, bit) order
    {
        int ow = s_wsum[wid] + wexc;
        int ob = s_bsum[wid] + bexc;
        #pragma unroll
        for (int k = 0; k < 5; k++) {
            unsigned m = ww[k];
            const int w = k * 256 + tid;
            while (m) {
                const int j = __ffs(m) - 1;
                m &= m - 1u;
                if (ow < CAP) s_idxW[ow] = decode_f(w, j);
                ow++;
            }
            m = bw[k];
            while (m) {
                const int j = __ffs(m) - 1;
                m &= m - 1u;
                if (ob < CAP) s_idxB[ob] = decode_f(w, j);
                ob++;
            }
        }
    }
    __syncthreads();

    // gather-accumulate: thread tid owns output m = tid. Unroll 8 for MLP.
    const float bias = ft_b[tid];
    float accW = bias, accB = bias;
    {
        const int nW = s_nW;
        int j = 0;
        for (; j + 8 <= nW; j += 8) {
            float a0 = g_ftwT[(size_t)s_idxW[j + 0] * MDIM + tid];
            float a1 = g_ftwT[(size_t)s_idxW[j + 1] * MDIM + tid];
            float a2 = g_ftwT[(size_t)s_idxW[j + 2] * MDIM + tid];
            float a3 = g_ftwT[(size_t)s_idxW[j + 3] * MDIM + tid];
            float a4 = g_ftwT[(size_t)s_idxW[j + 4] * MDIM + tid];
            float a5 = g_ftwT[(size_t)s_idxW[j + 5] * MDIM + tid];
            float a6 = g_ftwT[(size_t)s_idxW[j + 6] * MDIM + tid];
            float a7 = g_ftwT[(size_t)s_idxW[j + 7] * MDIM + tid];
            accW += a0; accW += a1; accW += a2; accW += a3;
            accW += a4; accW += a5; accW += a6; accW += a7;
        }
        for (; j < nW; j++) accW += g_ftwT[(size_t)s_idxW[j] * MDIM + tid];

        const int nB = s_nB;
        j = 0;
        for (; j + 8 <= nB; j += 8) {
            float a0 = g_ftwT[(size_t)s_idxB[j + 0] * MDIM + tid];
            float a1 = g_ftwT[(size_t)s_idxB[j + 1] * MDIM + tid];
            float a2 = g_ftwT[(size_t)s_idxB[j + 2] * MDIM + tid];
            float a3 = g_ftwT[(size_t)s_idxB[j + 3] * MDIM + tid];
            float a4 = g_ftwT[(size_t)s_idxB[j + 4] * MDIM + tid];
            float a5 = g_ftwT[(size_t)s_idxB[j + 5] * MDIM + tid];
            float a6 = g_ftwT[(size_t)s_idxB[j + 6] * MDIM + tid];
            float a7 = g_ftwT[(size_t)s_idxB[j + 7] * MDIM + tid];
            accB += a0; accB += a1; accB += a2; accB += a3;
            accB += a4; accB += a5; accB += a6; accB += a7;
        }
        for (; j < nB; j++) accB += g_ftwT[(size_t)s_idxB[j] * MDIM + tid];
    }

    // stm blend + clip
    const float s  = stm[b];
    s_h[tid]       = clamp01(s * accW + (1.0f - s) * accB);
    s_h[256 + tid] = clamp01(s * accB + (1.0f - s) * accW);
    __syncthreads();

    // L1: 512 -> 32, warp-per-output (4 outputs per warp), coalesced rows.
    {
        const float4* hv = reinterpret_cast<const float4*>(s_h);
        #pragma unroll
        for (int r = 0; r < 4; r++) {
            const int n = wid * 4 + r;
            const float4* wr = reinterpret_cast<const float4*>(l1_w + n * 512);
            float p = 0.0f;
            #pragma unroll
            for (int i = 0; i < 4; i++) {
                const float4 a = wr[i * 32 + lane];
                const float4 x = hv[i * 32 + lane];
                p += a.x * x.x;
                p += a.y * x.y;
                p += a.z * x.z;
                p += a.w * x.w;
            }
            p += __shfl_down_sync(0xffffffffu, p, 16);
            p += __shfl_down_sync(0xffffffffu, p, 8);
            p += __shfl_down_sync(0xffffffffu, p, 4);
            p += __shfl_down_sync(0xffffffffu, p, 2);
            p += __shfl_down_sync(0xffffffffu, p, 1);
            if (lane == 0) s_l2x[n] = clamp01(p + l1_b[n]);
        }
    }
    __syncthreads();

    // L2 (32->32) from padded smem (conflict-free), L3 (32->1). Warp 0 only.
    if (tid < 32) {
        float q = l2_b[tid];
        #pragma unroll
        for (int k = 0; k < 32; k++) q += s_l2w[tid * 33 + k] * s_l2x[k];
        const float l3x = clamp01(q);
        float t = l3x * l3_w[tid];
        #pragma unroll
        for (int off = 16; off > 0; off >>= 1)
            t += __shfl_down_sync(0xffffffffu, t, off);
        if (tid == 0) {
            const float ev = clamp01(t + l3_b[0]);
            out[b] = (ev - 0.5f) * 2.0f * 10000.0f;
        }
    }
}

// ---------------------------------------------------------------------------
// Launch
// ---------------------------------------------------------------------------
extern "C" void kernel_launch(void* const* d_in, const int* in_sizes, int n_in,
                              void* d_out, int out_size)
{
    const float* wf    = (const float*)d_in[0];
    const float* bfeat = (const float*)d_in[1];
    const float* stm   = (const float*)d_in[2];
    const float* ft_w  = (const float*)d_in[3];
    const float* ft_b  = (const float*)d_in[4];
    const float* l1_w  = (const float*)d_in[5];
    const float* l1_b  = (const float*)d_in[6];
    const float* l2_w  = (const float*)d_in[7];
    const float* l2_b  = (const float*)d_in[8];
    const float* l3_w  = (const float*)d_in[9];
    const float* l3_b  = (const float*)d_in[10];
    float* out = (float*)d_out;

    // 1) Fused scan (bitmap) + transpose in one grid
    scan_transpose_kernel<<<SCAN_CTAS + TR_CTAS, 256>>>(wf, bfeat, ft_w);

    // 2) Decode + gather + MLP tail, one CTA per position
    gather_mlp_kernel<<<NB, 256>>>(stm, ft_b, l1_w, l1_b, l2_w, l2_b,
                                   l3_w, l3_b, out);
}